// round 8
// baseline (speedup 1.0000x reference)
#include <cuda_runtime.h>
#include <cuda_bf16.h>
#include <cstdint>

#define TT 512
#define BD 2
#define TOK 256
#define TPR 12
#define HID 32
#define INNER 256
#define ATT_SCALE 0.0625f
#define BN_EPS 1e-5f

// ---------------- scratch (device globals: no allocation allowed) ----------
__device__ float g_w1f[TPR * HID];
__device__ float g_c1[HID];
__device__ float g_c2[TOK];
__device__ uint32_t g_bi1[TOK * 8];   // w2^T b1-limb, s8 k-packed [n][k/4]
__device__ uint32_t g_bi0[TOK * 8];   // b0-limb (centered, [-64,64])
__device__ float g_tc[TOK];           // per-column scale
__device__ float g_xb[BD * TT * TOK];
__device__ float g_qkv[BD * TT * 3 * INNER];
__device__ float g_dots[BD * TT * TT];

__device__ __forceinline__ uint32_t pack4s8(int x0, int x1, int x2, int x3) {
    return (uint32_t)(x0 & 0xff) | ((uint32_t)(x1 & 0xff) << 8) |
           ((uint32_t)(x2 & 0xff) << 16) | ((uint32_t)(x3 & 0xff) << 24);
}

// mma.sync m16n8k32 s8 (baseline PTX, works on sm_103)
__device__ __forceinline__ void mmaI(int* d, const uint32_t* a, const uint32_t* b) {
    asm volatile(
        "mma.sync.aligned.m16n8k32.row.col.s32.s8.s8.s32 "
        "{%0,%1,%2,%3}, {%4,%5,%6,%7}, {%8,%9}, {%0,%1,%2,%3};"
        : "+r"(d[0]), "+r"(d[1]), "+r"(d[2]), "+r"(d[3])
        : "r"(a[0]), "r"(a[1]), "r"(a[2]), "r"(a[3]), "r"(b[0]), "r"(b[1]));
}

// ---------------- setup: fold BN, quantize w2 to two s8 limbs ---------------
__global__ void setup_kernel(const float* __restrict__ w1, const float* __restrict__ b1,
                             const float* __restrict__ g1, const float* __restrict__ be1,
                             const float* __restrict__ m1, const float* __restrict__ v1,
                             const float* __restrict__ w2, const float* __restrict__ b2,
                             const float* __restrict__ g2, const float* __restrict__ be2,
                             const float* __restrict__ m2, const float* __restrict__ v2) {
    __shared__ float A1s[HID];
    int tid = threadIdx.x;
    if (tid < HID) {
        float a = g1[tid] * rsqrtf(v1[tid] + BN_EPS);
        A1s[tid] = a;
        g_c1[tid] = (b1[tid] - m1[tid]) * a + be1[tid];
    }
    __syncthreads();
    for (int i = tid; i < TPR * HID; i += blockDim.x) g_w1f[i] = w1[i] * A1s[i % HID];

    // one thread per output column c
    if (tid < TOK) {
        int c = tid;
        float a2 = g2[c] * rsqrtf(v2[c] + BN_EPS);
        g_c2[c] = (b2[c] - m2[c]) * a2 + be2[c];
        float wv[HID];
        float cm = 0.f;
#pragma unroll
        for (int h = 0; h < HID; h++) {
            wv[h] = w2[h * TOK + c] * a2;
            cm = fmaxf(cm, fabsf(wv[h]));
        }
        float tc = (cm > 0.f) ? cm / 16256.f : 1.f;
        float inv = 1.f / tc;
        int b1i[HID], b0i[HID];
#pragma unroll
        for (int h = 0; h < HID; h++) {
            int W = __float2int_rn(wv[h] * inv);           // |W| <= 16256
            int hi = __float2int_rn((float)W * 0.0078125f); // round(W/128), |hi|<=127
            b1i[h] = hi;
            b0i[h] = W - (hi << 7);                         // in [-64,64]
        }
#pragma unroll
        for (int i = 0; i < 8; i++) {
            g_bi1[c * 8 + i] = pack4s8(b1i[4 * i], b1i[4 * i + 1], b1i[4 * i + 2], b1i[4 * i + 3]);
            g_bi0[c * 8 + i] = pack4s8(b0i[4 * i], b0i[4 * i + 1], b0i[4 * i + 2], b0i[4 * i + 3]);
        }
        g_tc[c] = tc;
    }
}

// ---------------- fused TPR MLP (int8 IMMA) + max + (x+bias) ---------------
// smA1/smA0: [512][12] u32 (stride 12: 12g+tig mod 32 covers all banks).
#define A_STRIDE 12
extern __shared__ uint32_t sm_u[];
__global__ __launch_bounds__(256, 2)
void fused_tpr_kernel(const float* __restrict__ r, const float* __restrict__ x) {
    uint32_t* smA1 = sm_u;                      // [512][12]
    uint32_t* smA0 = sm_u + TT * A_STRIDE;      // [512][12]
    float* smS = (float*)(sm_u + 2 * TT * A_STRIDE);  // [512] per-row scales
    __shared__ float W1s[TPR * HID], C1s[HID];
    const int tid = threadIdx.x;
    const int bs = blockIdx.x;

    for (int i = tid; i < TPR * HID; i += 256) W1s[i] = g_w1f[i];
    if (tid < HID) C1s[tid] = g_c1[tid];
    __syncthreads();

    // Phase A: stage-1 MLP, 2 t-rows/thread, quantize row to two s8 limbs
    const float* rbase = r + (size_t)bs * TT * TPR;
#pragma unroll
    for (int tt = 0; tt < 2; tt++) {
        int t = tid + tt * 256;
        float rv[TPR];
#pragma unroll
        for (int d = 0; d < TPR; d++) rv[d] = rbase[(size_t)t * TPR + d];
        float hv[HID];
        float rmax = 0.f;
#pragma unroll
        for (int h = 0; h < HID; h++) {
            float acc = C1s[h];
#pragma unroll
            for (int d = 0; d < TPR; d++) acc = fmaf(rv[d], W1s[d * HID + h], acc);
            hv[h] = fmaxf(acc, 0.f);
            rmax = fmaxf(rmax, hv[h]);
        }
        float inv = (rmax > 0.f) ? 16383.f / rmax : 0.f;
        int a1[HID], a0[HID];
#pragma unroll
        for (int h = 0; h < HID; h++) {
            int H = __float2int_rn(hv[h] * inv);   // 0..16383
            a1[h] = H >> 7;                        // 0..127
            a0[h] = H & 127;                       // 0..127
        }
#pragma unroll
        for (int i = 0; i < 8; i++) {
            smA1[t * A_STRIDE + i] = pack4s8(a1[4 * i], a1[4 * i + 1], a1[4 * i + 2], a1[4 * i + 3]);
            smA0[t * A_STRIDE + i] = pack4s8(a0[4 * i], a0[4 * i + 1], a0[4 * i + 2], a0[4 * i + 3]);
        }
        smS[t] = rmax * (1.f / 16383.f);
    }

    // B fragments + column scales: straight from global (L2-hot), once per warp
    const int wid = tid >> 5, lane = tid & 31;
    const int g = lane >> 2, tig = lane & 3;
    const int nb = wid * 32;
    uint32_t B1f[4][2], B0f[4][2];
    float tcr[4][2];
#pragma unroll
    for (int sub = 0; sub < 4; sub++) {
        int n = nb + sub * 8 + g;
        B1f[sub][0] = g_bi1[n * 8 + tig];     B1f[sub][1] = g_bi1[n * 8 + 4 + tig];
        B0f[sub][0] = g_bi0[n * 8 + tig];     B0f[sub][1] = g_bi0[n * 8 + 4 + tig];
        tcr[sub][0] = g_tc[nb + sub * 8 + 2 * tig];
        tcr[sub][1] = g_tc[nb + sub * 8 + 2 * tig + 1];
    }
    __syncthreads();

    float mx[4][2];
#pragma unroll
    for (int sub = 0; sub < 4; sub++) { mx[sub][0] = -3.4e38f; mx[sub][1] = -3.4e38f; }

    for (int mi = 0; mi < 32; mi++) {
        const int r0 = mi * 16 + g;
        uint32_t A1[4], A0[4];
        A1[0] = smA1[r0 * A_STRIDE + tig];       A1[1] = smA1[(r0 + 8) * A_STRIDE + tig];
        A1[2] = smA1[r0 * A_STRIDE + 4 + tig];   A1[3] = smA1[(r0 + 8) * A_STRIDE + 4 + tig];
        A0[0] = smA0[r0 * A_STRIDE + tig];       A0[1] = smA0[(r0 + 8) * A_STRIDE + tig];
        A0[2] = smA0[r0 * A_STRIDE + 4 + tig];   A0[3] = smA0[(r0 + 8) * A_STRIDE + 4 + tig];
        float srow0 = smS[r0], srow1 = smS[r0 + 8];
#pragma unroll
        for (int sub = 0; sub < 4; sub++) {
            int p1[4] = {0, 0, 0, 0};
            int pc[4] = {0, 0, 0, 0};
            mmaI(p1, A1, B1f[sub]);   // a1*b1
            mmaI(pc, A1, B0f[sub]);   // a1*b0
            mmaI(pc, A0, B1f[sub]);   // + a0*b1
            float f0 = fmaf(16384.f, (float)p1[0], 128.f * (float)pc[0]) * srow0;
            float f1 = fmaf(16384.f, (float)p1[1], 128.f * (float)pc[1]) * srow0;
            float f2 = fmaf(16384.f, (float)p1[2], 128.f * (float)pc[2]) * srow1;
            float f3 = fmaf(16384.f, (float)p1[3], 128.f * (float)pc[3]) * srow1;
            mx[sub][0] = fmaxf(mx[sub][0], fmaxf(f0, f2));
            mx[sub][1] = fmaxf(mx[sub][1], fmaxf(f1, f3));
        }
    }
    // reduce over row-groups (same tig), apply column scale, write xb
#pragma unroll
    for (int sub = 0; sub < 4; sub++) {
#pragma unroll
        for (int j = 0; j < 2; j++) {
            float v = mx[sub][j];
            v = fmaxf(v, __shfl_xor_sync(0xffffffffu, v, 4));
            v = fmaxf(v, __shfl_xor_sync(0xffffffffu, v, 8));
            v = fmaxf(v, __shfl_xor_sync(0xffffffffu, v, 16));
            float tc = tcr[sub][j];
            tc = __shfl_sync(0xffffffffu, tc, lane & 3);  // keep lane<4's own value
            if (lane < 4) {
                int c = nb + sub * 8 + 2 * lane + j;
                g_xb[(size_t)bs * TOK + c] =
                    x[(size_t)bs * TOK + c] + fmaxf(v * tc + g_c2[c], 0.f);
            }
        }
    }
}

// ---------------- qkv = xb @ w_qkv  [1024,256]x[256,768] --------------------
__global__ void qkv_kernel(const float* __restrict__ w_qkv) {
    __shared__ float As[16][64];
    __shared__ float Bs[16][64];
    const int tid = threadIdx.x;
    const int tx = tid & 15, ty = tid >> 4;
    const int m0 = blockIdx.y * 64, n0 = blockIdx.x * 64;
    float acc[4][4] = {};
    float pa[4], pb[4];
#pragma unroll
    for (int i = 0; i < 4; i++) {
        int idx = tid + i * 256;
        int row = idx >> 4, kk = idx & 15;
        pa[i] = g_xb[(size_t)(m0 + row) * TOK + kk];
        int bk2 = idx >> 6, bn2 = idx & 63;
        pb[i] = w_qkv[(size_t)(bk2) * 768 + n0 + bn2];
    }
    for (int k0 = 0; k0 < TOK; k0 += 16) {
#pragma unroll
        for (int i = 0; i < 4; i++) {
            int idx = tid + i * 256;
            int row = idx >> 4, kk = idx & 15;
            As[kk][row] = pa[i];
            int bk2 = idx >> 6, bn2 = idx & 63;
            Bs[bk2][bn2] = pb[i];
        }
        __syncthreads();
        if (k0 + 16 < TOK) {
#pragma unroll
            for (int i = 0; i < 4; i++) {
                int idx = tid + i * 256;
                int row = idx >> 4, kk = idx & 15;
                pa[i] = g_xb[(size_t)(m0 + row) * TOK + k0 + 16 + kk];
                int bk2 = idx >> 6, bn2 = idx & 63;
                pb[i] = w_qkv[(size_t)(k0 + 16 + bk2) * 768 + n0 + bn2];
            }
        }
#pragma unroll
        for (int kk = 0; kk < 16; kk++) {
            float a[4], b[4];
#pragma unroll
            for (int i = 0; i < 4; i++) { a[i] = As[kk][ty * 4 + i]; b[i] = Bs[kk][tx * 4 + i]; }
#pragma unroll
            for (int i = 0; i < 4; i++)
#pragma unroll
                for (int j = 0; j < 4; j++) acc[i][j] = fmaf(a[i], b[j], acc[i][j]);
        }
        __syncthreads();
    }
#pragma unroll
    for (int i = 0; i < 4; i++)
#pragma unroll
        for (int j = 0; j < 4; j++)
            g_qkv[(size_t)(m0 + ty * 4 + i) * 768 + n0 + tx * 4 + j] = acc[i][j];
}

// ---------------- dots = q @ k^T * scale ------------------------------------
__global__ void dots_kernel() {
    __shared__ float As[16][64];
    __shared__ float Bs[16][64];
    const int tid = threadIdx.x;
    const int tx = tid & 15, ty = tid >> 4;
    const int b = blockIdx.z;
    const int m0 = blockIdx.x * 64, n0 = blockIdx.y * 64;
    const float* q = g_qkv + (size_t)b * TT * 768;
    const float* k = g_qkv + (size_t)b * TT * 768 + INNER;
    float acc[4][4] = {};
    float pa[4], pb[4];
#pragma unroll
    for (int i = 0; i < 4; i++) {
        int idx = tid + i * 256;
        int row = idx >> 4, kk = idx & 15;
        pa[i] = q[(size_t)(m0 + row) * 768 + kk];
        pb[i] = k[(size_t)(n0 + row) * 768 + kk];
    }
    for (int k0 = 0; k0 < INNER; k0 += 16) {
#pragma unroll
        for (int i = 0; i < 4; i++) {
            int idx = tid + i * 256;
            int row = idx >> 4, kk = idx & 15;
            As[kk][row] = pa[i];
            Bs[kk][row] = pb[i];
        }
        __syncthreads();
        if (k0 + 16 < INNER) {
#pragma unroll
            for (int i = 0; i < 4; i++) {
                int idx = tid + i * 256;
                int row = idx >> 4, kk = idx & 15;
                pa[i] = q[(size_t)(m0 + row) * 768 + k0 + 16 + kk];
                pb[i] = k[(size_t)(n0 + row) * 768 + k0 + 16 + kk];
            }
        }
#pragma unroll
        for (int kk = 0; kk < 16; kk++) {
            float a[4], bb[4];
#pragma unroll
            for (int i = 0; i < 4; i++) { a[i] = As[kk][ty * 4 + i]; bb[i] = Bs[kk][tx * 4 + i]; }
#pragma unroll
            for (int i = 0; i < 4; i++)
#pragma unroll
                for (int j = 0; j < 4; j++) acc[i][j] = fmaf(a[i], bb[j], acc[i][j]);
        }
        __syncthreads();
    }
    float* dst = g_dots + (size_t)b * TT * TT;
#pragma unroll
    for (int i = 0; i < 4; i++)
#pragma unroll
        for (int j = 0; j < 4; j++)
            dst[(size_t)(m0 + ty * 4 + i) * TT + n0 + tx * 4 + j] = acc[i][j] * ATT_SCALE;
}

// ---------------- row softmax over 512 --------------------------------------
__global__ void softmax_kernel() {
    const int row = blockIdx.x;
    float* p = g_dots + (size_t)row * TT;
    const int tid = threadIdx.x;
    const int w = tid >> 5, l = tid & 31;
    float v[4];
#pragma unroll
    for (int i = 0; i < 4; i++) v[i] = p[tid + i * 128];
    float m = fmaxf(fmaxf(v[0], v[1]), fmaxf(v[2], v[3]));
#pragma unroll
    for (int o = 16; o; o >>= 1) m = fmaxf(m, __shfl_xor_sync(0xffffffffu, m, o));
    __shared__ float red[4], red2[4];
    if (!l) red[w] = m;
    __syncthreads();
    m = fmaxf(fmaxf(red[0], red[1]), fmaxf(red[2], red[3]));
    float s = 0.f;
#pragma unroll
    for (int i = 0; i < 4; i++) { v[i] = __expf(v[i] - m); s += v[i]; }
#pragma unroll
    for (int o = 16; o; o >>= 1) s += __shfl_xor_sync(0xffffffffu, s, o);
    if (!l) red2[w] = s;
    __syncthreads();
    s = red2[0] + red2[1] + red2[2] + red2[3];
    float inv = 1.f / s;
#pragma unroll
    for (int i = 0; i < 4; i++) p[tid + i * 128] = v[i] * inv;
}

// ---------------- out = attn @ v ---------------------------------------------
__global__ void out_kernel(float* __restrict__ out) {
    __shared__ float As[16][64];
    __shared__ float Bs[16][64];
    const int tid = threadIdx.x;
    const int tx = tid & 15, ty = tid >> 4;
    const int b = blockIdx.z;
    const int m0 = blockIdx.y * 64, n0 = blockIdx.x * 64;
    const float* attn = g_dots + (size_t)b * TT * TT;
    const float* v = g_qkv + (size_t)b * TT * 768 + 2 * INNER;
    float acc[4][4] = {};
    float pa[4], pb[4];
#pragma unroll
    for (int i = 0; i < 4; i++) {
        int idx = tid + i * 256;
        int row = idx >> 4, kk = idx & 15;
        pa[i] = attn[(size_t)(m0 + row) * TT + kk];
        int bk2 = idx >> 6, bn2 = idx & 63;
        pb[i] = v[(size_t)(bk2) * 768 + n0 + bn2];
    }
    for (int k0 = 0; k0 < TT; k0 += 16) {
#pragma unroll
        for (int i = 0; i < 4; i++) {
            int idx = tid + i * 256;
            int row = idx >> 4, kk = idx & 15;
            As[kk][row] = pa[i];
            int bk2 = idx >> 6, bn2 = idx & 63;
            Bs[bk2][bn2] = pb[i];
        }
        __syncthreads();
        if (k0 + 16 < TT) {
#pragma unroll
            for (int i = 0; i < 4; i++) {
                int idx = tid + i * 256;
                int row = idx >> 4, kk = idx & 15;
                pa[i] = attn[(size_t)(m0 + row) * TT + k0 + 16 + kk];
                int bk2 = idx >> 6, bn2 = idx & 63;
                pb[i] = v[(size_t)(k0 + 16 + bk2) * 768 + n0 + bn2];
            }
        }
#pragma unroll
        for (int kk = 0; kk < 16; kk++) {
            float a[4], bb[4];
#pragma unroll
            for (int i = 0; i < 4; i++) { a[i] = As[kk][ty * 4 + i]; bb[i] = Bs[kk][tx * 4 + i]; }
#pragma unroll
            for (int i = 0; i < 4; i++)
#pragma unroll
                for (int j = 0; j < 4; j++) acc[i][j] = fmaf(a[i], bb[j], acc[i][j]);
        }
        __syncthreads();
    }
#pragma unroll
    for (int i = 0; i < 4; i++)
#pragma unroll
        for (int j = 0; j < 4; j++)
            out[(size_t)(b * TT + m0 + ty * 4 + i) * INNER + n0 + tx * 4 + j] = acc[i][j];
}

// ---------------- launch ------------------------------------------------------
extern "C" void kernel_launch(void* const* d_in, const int* in_sizes, int n_in,
                              void* d_out, int out_size) {
    const float* x     = (const float*)d_in[0];
    const float* r     = (const float*)d_in[1];
    const float* w1    = (const float*)d_in[2];
    const float* b1    = (const float*)d_in[3];
    const float* g1    = (const float*)d_in[4];
    const float* be1   = (const float*)d_in[5];
    const float* m1    = (const float*)d_in[6];
    const float* v1    = (const float*)d_in[7];
    const float* w2    = (const float*)d_in[8];
    const float* b2    = (const float*)d_in[9];
    const float* g2    = (const float*)d_in[10];
    const float* be2   = (const float*)d_in[11];
    const float* m2    = (const float*)d_in[12];
    const float* v2    = (const float*)d_in[13];
    const float* w_qkv = (const float*)d_in[14];
    float* out = (float*)d_out;

    setup_kernel<<<1, 256>>>(w1, b1, g1, be1, m1, v1, w2, b2, g2, be2, m2, v2);

    int smem_bytes = (2 * TT * A_STRIDE + TT) * (int)sizeof(uint32_t); // 51200
    cudaFuncSetAttribute(fused_tpr_kernel, cudaFuncAttributeMaxDynamicSharedMemorySize, smem_bytes);
    fused_tpr_kernel<<<BD * TT, 256, smem_bytes>>>(r, x);

    qkv_kernel<<<dim3(768 / 64, 1024 / 64), 256>>>(w_qkv);
    dots_kernel<<<dim3(TT / 64, TT / 64, BD), 256>>>();
    softmax_kernel<<<BD * TT, 128>>>();
    out_kernel<<<dim3(INNER / 64, TT / 64, BD), 256>>>(out);
}

// round 9
// speedup vs baseline: 1.1848x; 1.1848x over previous
#include <cuda_runtime.h>
#include <cuda_bf16.h>
#include <cstdint>

#define TT 512
#define BD 2
#define TOK 256
#define TPR 12
#define HID 32
#define INNER 256
#define ATT_SCALE 0.0625f
#define BN_EPS 1e-5f

// ---------------- scratch (device globals: no allocation allowed) ----------
__device__ float g_w1f[TPR * HID];
__device__ float g_c1[HID];
__device__ float g_c2[TOK];
__device__ uint32_t g_bi1[TOK * 8];   // w2^T b1-limb, s8 k-packed [n][k/4]
__device__ uint32_t g_bi0[TOK * 8];   // b0-limb (centered, [-64,64])
__device__ float g_tc[TOK];           // per-column scale
__device__ float g_xb[BD * TT * TOK];
__device__ float g_qkv[BD * TT * 3 * INNER];
__device__ float g_dots[BD * TT * TT];

__device__ __forceinline__ uint32_t pack4s8(int x0, int x1, int x2, int x3) {
    return (uint32_t)(x0 & 0xff) | ((uint32_t)(x1 & 0xff) << 8) |
           ((uint32_t)(x2 & 0xff) << 16) | ((uint32_t)(x3 & 0xff) << 24);
}

// mma.sync m16n8k32 s8 (baseline PTX, works on sm_103)
__device__ __forceinline__ void mmaI(int* d, const uint32_t* a, const uint32_t* b) {
    asm volatile(
        "mma.sync.aligned.m16n8k32.row.col.s32.s8.s8.s32 "
        "{%0,%1,%2,%3}, {%4,%5,%6,%7}, {%8,%9}, {%0,%1,%2,%3};"
        : "+r"(d[0]), "+r"(d[1]), "+r"(d[2]), "+r"(d[3])
        : "r"(a[0]), "r"(a[1]), "r"(a[2]), "r"(a[3]), "r"(b[0]), "r"(b[1]));
}

// ---------------- setup: fold BN, quantize w2 to two s8 limbs ---------------
__global__ void setup_kernel(const float* __restrict__ w1, const float* __restrict__ b1,
                             const float* __restrict__ g1, const float* __restrict__ be1,
                             const float* __restrict__ m1, const float* __restrict__ v1,
                             const float* __restrict__ w2, const float* __restrict__ b2,
                             const float* __restrict__ g2, const float* __restrict__ be2,
                             const float* __restrict__ m2, const float* __restrict__ v2) {
    __shared__ float A1s[HID];
    int tid = threadIdx.x;
    if (tid < HID) {
        float a = g1[tid] * rsqrtf(v1[tid] + BN_EPS);
        A1s[tid] = a;
        g_c1[tid] = (b1[tid] - m1[tid]) * a + be1[tid];
    }
    __syncthreads();
    for (int i = tid; i < TPR * HID; i += blockDim.x) g_w1f[i] = w1[i] * A1s[i % HID];

    if (tid < TOK) {
        int c = tid;
        float a2 = g2[c] * rsqrtf(v2[c] + BN_EPS);
        g_c2[c] = (b2[c] - m2[c]) * a2 + be2[c];
        float wv[HID];
        float cm = 0.f;
#pragma unroll
        for (int h = 0; h < HID; h++) {
            wv[h] = w2[h * TOK + c] * a2;
            cm = fmaxf(cm, fabsf(wv[h]));
        }
        float tc = (cm > 0.f) ? cm / 16256.f : 1.f;
        float inv = 1.f / tc;
        int b1i[HID], b0i[HID];
#pragma unroll
        for (int h = 0; h < HID; h++) {
            int W = __float2int_rn(wv[h] * inv);            // |W| <= 16256
            int hi = __float2int_rn((float)W * 0.0078125f); // round(W/128)
            b1i[h] = hi;
            b0i[h] = W - (hi << 7);                         // in [-64,64]
        }
#pragma unroll
        for (int i = 0; i < 8; i++) {
            g_bi1[c * 8 + i] = pack4s8(b1i[4 * i], b1i[4 * i + 1], b1i[4 * i + 2], b1i[4 * i + 3]);
            g_bi0[c * 8 + i] = pack4s8(b0i[4 * i], b0i[4 * i + 1], b0i[4 * i + 2], b0i[4 * i + 3]);
        }
        g_tc[c] = tc;
    }
}

// ---------------- fused TPR MLP (int8 IMMA, block scale, int max) -----------
#define A_STRIDE 12
extern __shared__ uint32_t sm_u[];
__global__ __launch_bounds__(256, 2)
void fused_tpr_kernel(const float* __restrict__ r, const float* __restrict__ x) {
    uint32_t* smA1 = sm_u;                      // [512][12]
    uint32_t* smA0 = sm_u + TT * A_STRIDE;      // [512][12]
    __shared__ float W1s[TPR * HID], C1s[HID];
    __shared__ float red[8];
    const int tid = threadIdx.x, bs = blockIdx.x;
    const int wid = tid >> 5, lane = tid & 31;

    for (int i = tid; i < TPR * HID; i += 256) W1s[i] = g_w1f[i];
    if (tid < HID) C1s[tid] = g_c1[tid];
    __syncthreads();

    // Load both r rows (t = tid, tid+256) once, keep in registers.
    float rv[2][TPR];
#pragma unroll
    for (int tt = 0; tt < 2; tt++) {
        int t = tid + tt * 256;
        const float4* rp = reinterpret_cast<const float4*>(
            r + (size_t)bs * TT * TPR + (size_t)t * TPR);
        float4 v0 = rp[0], v1 = rp[1], v2 = rp[2];
        rv[tt][0] = v0.x; rv[tt][1] = v0.y; rv[tt][2] = v0.z; rv[tt][3] = v0.w;
        rv[tt][4] = v1.x; rv[tt][5] = v1.y; rv[tt][6] = v1.z; rv[tt][7] = v1.w;
        rv[tt][8] = v2.x; rv[tt][9] = v2.y; rv[tt][10] = v2.z; rv[tt][11] = v2.w;
    }

    // Pass 1: block-wide max of relu(h1)   (rmax init 0 folds the relu)
    float rmax = 0.f;
#pragma unroll
    for (int tt = 0; tt < 2; tt++)
#pragma unroll
        for (int h = 0; h < HID; h++) {
            float acc = C1s[h];
#pragma unroll
            for (int d = 0; d < TPR; d++) acc = fmaf(rv[tt][d], W1s[d * HID + h], acc);
            rmax = fmaxf(rmax, acc);
        }
#pragma unroll
    for (int o = 16; o; o >>= 1) rmax = fmaxf(rmax, __shfl_xor_sync(0xffffffffu, rmax, o));
    if (lane == 0) red[wid] = rmax;
    __syncthreads();
    float gmax = red[0];
#pragma unroll
    for (int i = 1; i < 8; i++) gmax = fmaxf(gmax, red[i]);
    const float qinv = (gmax > 0.f) ? 16383.f / gmax : 0.f;

    // Pass 2: recompute h1, quantize to two 7-bit limbs, pack to smem
#pragma unroll
    for (int tt = 0; tt < 2; tt++) {
        int t = tid + tt * 256;
        uint32_t w1p = 0, w0p = 0;
#pragma unroll
        for (int h = 0; h < HID; h++) {
            float acc = C1s[h];
#pragma unroll
            for (int d = 0; d < TPR; d++) acc = fmaf(rv[tt][d], W1s[d * HID + h], acc);
            int H = __float2int_rn(fmaxf(acc, 0.f) * qinv);   // 0..16383 exact
            int sh = 8 * (h & 3);
            w1p |= (uint32_t)(H >> 7) << sh;
            w0p |= (uint32_t)(H & 127) << sh;
            if ((h & 3) == 3) {
                smA1[t * A_STRIDE + (h >> 2)] = w1p;
                smA0[t * A_STRIDE + (h >> 2)] = w0p;
                w1p = w0p = 0;
            }
        }
    }

    // B fragments once per warp from global (L2-hot)
    const int g = lane >> 2, tig = lane & 3;
    const int nb = wid * 32;
    uint32_t B1f[4][2], B0f[4][2];
#pragma unroll
    for (int sub = 0; sub < 4; sub++) {
        int n = nb + sub * 8 + g;
        B1f[sub][0] = g_bi1[n * 8 + tig];   B1f[sub][1] = g_bi1[n * 8 + 4 + tig];
        B0f[sub][0] = g_bi0[n * 8 + tig];   B0f[sub][1] = g_bi0[n * 8 + 4 + tig];
    }
    __syncthreads();

    // Phase B: IMMA + pure-integer column max (block scale makes it legal)
    int imx[4][2];
#pragma unroll
    for (int sub = 0; sub < 4; sub++) { imx[sub][0] = -2147483647 - 1; imx[sub][1] = -2147483647 - 1; }

    for (int mi = 0; mi < 32; mi++) {
        const int r0 = mi * 16 + g;
        uint32_t A1[4], A0[4];
        A1[0] = smA1[r0 * A_STRIDE + tig];       A1[1] = smA1[(r0 + 8) * A_STRIDE + tig];
        A1[2] = smA1[r0 * A_STRIDE + 4 + tig];   A1[3] = smA1[(r0 + 8) * A_STRIDE + 4 + tig];
        A0[0] = smA0[r0 * A_STRIDE + tig];       A0[1] = smA0[(r0 + 8) * A_STRIDE + tig];
        A0[2] = smA0[r0 * A_STRIDE + 4 + tig];   A0[3] = smA0[(r0 + 8) * A_STRIDE + 4 + tig];
#pragma unroll
        for (int sub = 0; sub < 4; sub++) {
            int p1[4] = {0, 0, 0, 0};
            int pc[4] = {0, 0, 0, 0};
            mmaI(p1, A1, B1f[sub]);   // a1*b1
            mmaI(pc, A1, B0f[sub]);   // a1*b0
            mmaI(pc, A0, B1f[sub]);   // + a0*b1
#pragma unroll
            for (int j = 0; j < 2; j++) {
                int c0 = p1[j] * 128 + pc[j];            // row r0+g   (<2^26)
                int c1 = p1[j + 2] * 128 + pc[j + 2];    // row r0+g+8
                imx[sub][j] = max(imx[sub][j], max(c0, c1));
            }
        }
    }
    const float scale = 128.f * gmax * (1.f / 16383.f);
#pragma unroll
    for (int sub = 0; sub < 4; sub++)
#pragma unroll
        for (int j = 0; j < 2; j++) {
            int v = imx[sub][j];
            v = max(v, __shfl_xor_sync(0xffffffffu, v, 4));
            v = max(v, __shfl_xor_sync(0xffffffffu, v, 8));
            v = max(v, __shfl_xor_sync(0xffffffffu, v, 16));
            if (lane < 4) {
                int c = nb + sub * 8 + 2 * lane + j;
                float f = (float)v * scale * g_tc[c];
                g_xb[(size_t)bs * TOK + c] =
                    x[(size_t)bs * TOK + c] + fmaxf(f + g_c2[c], 0.f);
            }
        }
}

// ---------------- qkv = xb @ w_qkv  [1024,256]x[256,768] --------------------
__global__ void qkv_kernel(const float* __restrict__ w_qkv) {
    __shared__ float As[16][65];   // +1 pad: kills 16-way store conflicts
    __shared__ float Bs[16][64];
    const int tid = threadIdx.x;
    const int tx = tid & 15, ty = tid >> 4;
    const int m0 = blockIdx.y * 64, n0 = blockIdx.x * 64;
    float acc[4][4] = {};
    float pa[4], pb[4];
#pragma unroll
    for (int i = 0; i < 4; i++) {
        int idx = tid + i * 256;
        pa[i] = g_xb[(size_t)(m0 + (idx >> 4)) * TOK + (idx & 15)];
        pb[i] = w_qkv[(size_t)(idx >> 6) * 768 + n0 + (idx & 63)];
    }
    for (int k0 = 0; k0 < TOK; k0 += 16) {
#pragma unroll
        for (int i = 0; i < 4; i++) {
            int idx = tid + i * 256;
            As[idx & 15][idx >> 4] = pa[i];
            Bs[idx >> 6][idx & 63] = pb[i];
        }
        __syncthreads();
        if (k0 + 16 < TOK) {
#pragma unroll
            for (int i = 0; i < 4; i++) {
                int idx = tid + i * 256;
                pa[i] = g_xb[(size_t)(m0 + (idx >> 4)) * TOK + k0 + 16 + (idx & 15)];
                pb[i] = w_qkv[(size_t)(k0 + 16 + (idx >> 6)) * 768 + n0 + (idx & 63)];
            }
        }
#pragma unroll
        for (int kk = 0; kk < 16; kk++) {
            float a[4], b[4];
#pragma unroll
            for (int i = 0; i < 4; i++) { a[i] = As[kk][ty * 4 + i]; b[i] = Bs[kk][tx * 4 + i]; }
#pragma unroll
            for (int i = 0; i < 4; i++)
#pragma unroll
                for (int j = 0; j < 4; j++) acc[i][j] = fmaf(a[i], b[j], acc[i][j]);
        }
        __syncthreads();
    }
#pragma unroll
    for (int i = 0; i < 4; i++)
#pragma unroll
        for (int j = 0; j < 4; j++)
            g_qkv[(size_t)(m0 + ty * 4 + i) * 768 + n0 + tx * 4 + j] = acc[i][j];
}

// ---------------- dots = q @ k^T * scale  (32x64 tiles, 128 thr) ------------
__global__ __launch_bounds__(128) void dots_kernel() {
    __shared__ float As[16][33];
    __shared__ float Bs[16][65];
    const int tid = threadIdx.x;
    const int tx = tid & 15, ty = tid >> 4;   // tx: n (16x4), ty: m (8x4)
    const int b = blockIdx.z;
    const int m0 = blockIdx.x * 32, n0 = blockIdx.y * 64;
    const float* q = g_qkv + (size_t)b * TT * 768;
    const float* k = g_qkv + (size_t)b * TT * 768 + INNER;
    float acc[4][4] = {};
    float pa[4], pb[8];
#pragma unroll
    for (int i = 0; i < 4; i++) {
        int idx = tid + i * 128;
        pa[i] = q[(size_t)(m0 + (idx >> 4)) * 768 + (idx & 15)];
    }
#pragma unroll
    for (int i = 0; i < 8; i++) {
        int idx = tid + i * 128;
        pb[i] = k[(size_t)(n0 + (idx >> 4)) * 768 + (idx & 15)];
    }
    for (int k0 = 0; k0 < INNER; k0 += 16) {
#pragma unroll
        for (int i = 0; i < 4; i++) { int idx = tid + i * 128; As[idx & 15][idx >> 4] = pa[i]; }
#pragma unroll
        for (int i = 0; i < 8; i++) { int idx = tid + i * 128; Bs[idx & 15][idx >> 4] = pb[i]; }
        __syncthreads();
        if (k0 + 16 < INNER) {
#pragma unroll
            for (int i = 0; i < 4; i++) {
                int idx = tid + i * 128;
                pa[i] = q[(size_t)(m0 + (idx >> 4)) * 768 + k0 + 16 + (idx & 15)];
            }
#pragma unroll
            for (int i = 0; i < 8; i++) {
                int idx = tid + i * 128;
                pb[i] = k[(size_t)(n0 + (idx >> 4)) * 768 + k0 + 16 + (idx & 15)];
            }
        }
#pragma unroll
        for (int kk = 0; kk < 16; kk++) {
            float a[4], bb[4];
#pragma unroll
            for (int i = 0; i < 4; i++) { a[i] = As[kk][ty * 4 + i]; bb[i] = Bs[kk][tx * 4 + i]; }
#pragma unroll
            for (int i = 0; i < 4; i++)
#pragma unroll
                for (int j = 0; j < 4; j++) acc[i][j] = fmaf(a[i], bb[j], acc[i][j]);
        }
        __syncthreads();
    }
    float* dst = g_dots + (size_t)b * TT * TT;
#pragma unroll
    for (int i = 0; i < 4; i++)
#pragma unroll
        for (int j = 0; j < 4; j++)
            dst[(size_t)(m0 + ty * 4 + i) * TT + n0 + tx * 4 + j] = acc[i][j] * ATT_SCALE;
}

// ---------------- row softmax over 512 --------------------------------------
__global__ void softmax_kernel() {
    const int row = blockIdx.x;
    float* p = g_dots + (size_t)row * TT;
    const int tid = threadIdx.x;
    const int w = tid >> 5, l = tid & 31;
    float v[4];
#pragma unroll
    for (int i = 0; i < 4; i++) v[i] = p[tid + i * 128];
    float m = fmaxf(fmaxf(v[0], v[1]), fmaxf(v[2], v[3]));
#pragma unroll
    for (int o = 16; o; o >>= 1) m = fmaxf(m, __shfl_xor_sync(0xffffffffu, m, o));
    __shared__ float red[4], red2[4];
    if (!l) red[w] = m;
    __syncthreads();
    m = fmaxf(fmaxf(red[0], red[1]), fmaxf(red[2], red[3]));
    float s = 0.f;
#pragma unroll
    for (int i = 0; i < 4; i++) { v[i] = __expf(v[i] - m); s += v[i]; }
#pragma unroll
    for (int o = 16; o; o >>= 1) s += __shfl_xor_sync(0xffffffffu, s, o);
    if (!l) red2[w] = s;
    __syncthreads();
    s = red2[0] + red2[1] + red2[2] + red2[3];
    float inv = 1.f / s;
#pragma unroll
    for (int i = 0; i < 4; i++) p[tid + i * 128] = v[i] * inv;
}

// ---------------- out = attn @ v  (32x64 tiles, 128 thr) --------------------
__global__ __launch_bounds__(128) void out_kernel(float* __restrict__ out) {
    __shared__ float As[16][33];
    __shared__ float Bs[16][65];
    const int tid = threadIdx.x;
    const int tx = tid & 15, ty = tid >> 4;   // tx: n (16x4), ty: m (8x4)
    const int b = blockIdx.z;
    const int m0 = blockIdx.y * 32, n0 = blockIdx.x * 64;
    const float* attn = g_dots + (size_t)b * TT * TT;
    const float* v = g_qkv + (size_t)b * TT * 768 + 2 * INNER;
    float acc[4][4] = {};
    float pa[4], pb[8];
#pragma unroll
    for (int i = 0; i < 4; i++) {
        int idx = tid + i * 128;
        pa[i] = attn[(size_t)(m0 + (idx >> 4)) * TT + (idx & 15)];
    }
#pragma unroll
    for (int i = 0; i < 8; i++) {
        int idx = tid + i * 128;
        pb[i] = v[(size_t)(idx >> 6) * 768 + n0 + (idx & 63)];
    }
    for (int k0 = 0; k0 < TT; k0 += 16) {
#pragma unroll
        for (int i = 0; i < 4; i++) { int idx = tid + i * 128; As[idx & 15][idx >> 4] = pa[i]; }
#pragma unroll
        for (int i = 0; i < 8; i++) { int idx = tid + i * 128; Bs[idx >> 6][idx & 63] = pb[i]; }
        __syncthreads();
        if (k0 + 16 < TT) {
#pragma unroll
            for (int i = 0; i < 4; i++) {
                int idx = tid + i * 128;
                pa[i] = attn[(size_t)(m0 + (idx >> 4)) * TT + k0 + 16 + (idx & 15)];
            }
#pragma unroll
            for (int i = 0; i < 8; i++) {
                int idx = tid + i * 128;
                pb[i] = v[(size_t)(k0 + 16 + (idx >> 6)) * 768 + n0 + (idx & 63)];
            }
        }
#pragma unroll
        for (int kk = 0; kk < 16; kk++) {
            float a[4], bb[4];
#pragma unroll
            for (int i = 0; i < 4; i++) { a[i] = As[kk][ty * 4 + i]; bb[i] = Bs[kk][tx * 4 + i]; }
#pragma unroll
            for (int i = 0; i < 4; i++)
#pragma unroll
                for (int j = 0; j < 4; j++) acc[i][j] = fmaf(a[i], bb[j], acc[i][j]);
        }
        __syncthreads();
    }
#pragma unroll
    for (int i = 0; i < 4; i++)
#pragma unroll
        for (int j = 0; j < 4; j++)
            out[(size_t)(b * TT + m0 + ty * 4 + i) * INNER + n0 + tx * 4 + j] = acc[i][j];
}

// ---------------- launch ------------------------------------------------------
extern "C" void kernel_launch(void* const* d_in, const int* in_sizes, int n_in,
                              void* d_out, int out_size) {
    const float* x     = (const float*)d_in[0];
    const float* r     = (const float*)d_in[1];
    const float* w1    = (const float*)d_in[2];
    const float* b1    = (const float*)d_in[3];
    const float* g1    = (const float*)d_in[4];
    const float* be1   = (const float*)d_in[5];
    const float* m1    = (const float*)d_in[6];
    const float* v1    = (const float*)d_in[7];
    const float* w2    = (const float*)d_in[8];
    const float* b2    = (const float*)d_in[9];
    const float* g2    = (const float*)d_in[10];
    const float* be2   = (const float*)d_in[11];
    const float* m2    = (const float*)d_in[12];
    const float* v2    = (const float*)d_in[13];
    const float* w_qkv = (const float*)d_in[14];
    float* out = (float*)d_out;

    setup_kernel<<<1, 256>>>(w1, b1, g1, be1, m1, v1, w2, b2, g2, be2, m2, v2);

    int smem_bytes = (2 * TT * A_STRIDE) * (int)sizeof(uint32_t); // 49152
    cudaFuncSetAttribute(fused_tpr_kernel, cudaFuncAttributeMaxDynamicSharedMemorySize, smem_bytes);
    fused_tpr_kernel<<<BD * TT, 256, smem_bytes>>>(r, x);

    qkv_kernel<<<dim3(768 / 64, 1024 / 64), 256>>>(w_qkv);
    dots_kernel<<<dim3(TT / 32, TT / 64, BD), 128>>>();
    softmax_kernel<<<BD * TT, 128>>>();
    out_kernel<<<dim3(INNER / 64, TT / 32, BD), 128>>>(out);
}

// round 10
// speedup vs baseline: 3.0157x; 2.5453x over previous
#include <cuda_runtime.h>
#include <cuda_fp16.h>
#include <cstdint>

#define TT 512
#define BD 2
#define TOK 256
#define TPR 12
#define HID 32
#define INNER 256
#define ATT_SCALE 0.0625f
#define BN_EPS 1e-5f

// ---------------- scratch (device globals: no allocation allowed) ----------
__device__ float g_w1f[TPR * HID];
__device__ float g_c1[HID];
__device__ float g_c2[TOK];
__device__ uint32_t g_w2h[TOK * 16];   // w2^T, BN-folded, f16 pairs [n][kpair]
__device__ float g_xb[BD * TT * TOK];
__device__ float g_qkv[BD * TT * 3 * INNER];
__device__ float g_dots[BD * TT * TT];

__device__ __forceinline__ uint32_t h2_bits(float a, float b) {
    __half2 h = __floats2half2_rn(a, b);
    return *reinterpret_cast<uint32_t*>(&h);
}

// mma.sync m16n8k16 f16 (baseline PTX, works on sm_103)
__device__ __forceinline__ void mmaH(float* d, const uint32_t* a, const uint32_t* b) {
    asm volatile(
        "mma.sync.aligned.m16n8k16.row.col.f32.f16.f16.f32 "
        "{%0,%1,%2,%3}, {%4,%5,%6,%7}, {%8,%9}, {%0,%1,%2,%3};"
        : "+f"(d[0]), "+f"(d[1]), "+f"(d[2]), "+f"(d[3])
        : "r"(a[0]), "r"(a[1]), "r"(a[2]), "r"(a[3]), "r"(b[0]), "r"(b[1]));
}

// ---------------- setup: fold BN into weights, f16 B tiles ------------------
__global__ void setup_kernel(const float* __restrict__ w1, const float* __restrict__ b1,
                             const float* __restrict__ g1, const float* __restrict__ be1,
                             const float* __restrict__ m1, const float* __restrict__ v1,
                             const float* __restrict__ w2, const float* __restrict__ b2,
                             const float* __restrict__ g2, const float* __restrict__ be2,
                             const float* __restrict__ m2, const float* __restrict__ v2) {
    __shared__ float A1s[HID], A2s[TOK];
    int tid = threadIdx.x;
    if (tid < HID) {
        float a = g1[tid] * rsqrtf(v1[tid] + BN_EPS);
        A1s[tid] = a;
        g_c1[tid] = (b1[tid] - m1[tid]) * a + be1[tid];
    }
    if (tid < TOK) {
        float a = g2[tid] * rsqrtf(v2[tid] + BN_EPS);
        A2s[tid] = a;
        g_c2[tid] = (b2[tid] - m2[tid]) * a + be2[tid];
    }
    __syncthreads();
    for (int i = tid; i < TPR * HID; i += blockDim.x) g_w1f[i] = w1[i] * A1s[i % HID];
    // w2^T pairs: entry i -> n = i>>4, kpair p = i&15 (h = 2p, 2p+1)
    for (int i = tid; i < TOK * 16; i += blockDim.x) {
        int n = i >> 4, p = i & 15;
        float wa = w2[(2 * p) * TOK + n] * A2s[n];
        float wb = w2[(2 * p + 1) * TOK + n] * A2s[n];
        g_w2h[i] = h2_bits(wa, wb);
    }
}

// ---------------- fused TPR MLP (single f16 HMMA) + max + (x+bias) ----------
#define H1_STRIDE 17   // u32 pairs per row (16 + 1 pad) -> conflict-free
extern __shared__ uint32_t sm_u[];
__global__ __launch_bounds__(256)
void fused_tpr_kernel(const float* __restrict__ r, const float* __restrict__ x) {
    uint32_t* smH = sm_u;                       // [512][17] f16 pairs
    __shared__ float W1s[TPR * HID], C1s[HID];
    const int tid = threadIdx.x;
    const int bs = blockIdx.x;

    for (int i = tid; i < TPR * HID; i += 256) W1s[i] = g_w1f[i];
    if (tid < HID) C1s[tid] = g_c1[tid];
    __syncthreads();

    // Phase A: stage-1 MLP, 2 t-rows per thread, relu, f16 pack
    const float* rbase = r + (size_t)bs * TT * TPR;
#pragma unroll
    for (int tt = 0; tt < 2; tt++) {
        int t = tid + tt * 256;
        const float4* rp = reinterpret_cast<const float4*>(rbase + (size_t)t * TPR);
        float4 v0 = rp[0], v1 = rp[1], v2 = rp[2];
        float rv[TPR] = {v0.x, v0.y, v0.z, v0.w, v1.x, v1.y, v1.z, v1.w,
                         v2.x, v2.y, v2.z, v2.w};
        float hv[HID];
#pragma unroll
        for (int h = 0; h < HID; h++) {
            float acc = C1s[h];
#pragma unroll
            for (int d = 0; d < TPR; d++) acc = fmaf(rv[d], W1s[d * HID + h], acc);
            hv[h] = fmaxf(acc, 0.f);
        }
#pragma unroll
        for (int p = 0; p < 16; p++)
            smH[t * H1_STRIDE + p] = h2_bits(hv[2 * p], hv[2 * p + 1]);
    }

    // B fragments once per warp from global (L2-hot)
    const int wid = tid >> 5, lane = tid & 31;
    const int g = lane >> 2, tig = lane & 3;
    const int nb = wid * 32;
    uint32_t Bh[4][4];   // [n-subtile][s*2 + reg]
#pragma unroll
    for (int sub = 0; sub < 4; sub++) {
        int n = nb + sub * 8 + g;
#pragma unroll
        for (int s = 0; s < 2; s++) {
            Bh[sub][s * 2 + 0] = g_w2h[n * 16 + tig + 8 * s];
            Bh[sub][s * 2 + 1] = g_w2h[n * 16 + tig + 4 + 8 * s];
        }
    }
    __syncthreads();

    // Phase B: single f16 product per tile; fold into per-column max
    float mx[4][2];
#pragma unroll
    for (int sub = 0; sub < 4; sub++) { mx[sub][0] = -3.4e38f; mx[sub][1] = -3.4e38f; }

    for (int mi = 0; mi < 32; mi++) {
        const int r0 = mi * 16 + g;
        uint32_t Ah[2][4];
#pragma unroll
        for (int s = 0; s < 2; s++) {
            int o0 = r0 * H1_STRIDE + tig + 8 * s;
            int o1 = (r0 + 8) * H1_STRIDE + tig + 8 * s;
            Ah[s][0] = smH[o0];     Ah[s][1] = smH[o1];
            Ah[s][2] = smH[o0 + 4]; Ah[s][3] = smH[o1 + 4];
        }
#pragma unroll
        for (int sub = 0; sub < 4; sub++) {
            float acc[4] = {0.f, 0.f, 0.f, 0.f};
            mmaH(acc, Ah[0], &Bh[sub][0]);
            mmaH(acc, Ah[1], &Bh[sub][2]);
            mx[sub][0] = fmaxf(mx[sub][0], fmaxf(acc[0], acc[2]));
            mx[sub][1] = fmaxf(mx[sub][1], fmaxf(acc[1], acc[3]));
        }
    }
    // reduce over row-groups (lanes with same tig), then write xb
#pragma unroll
    for (int sub = 0; sub < 4; sub++) {
#pragma unroll
        for (int j = 0; j < 2; j++) {
            float v = mx[sub][j];
            v = fmaxf(v, __shfl_xor_sync(0xffffffffu, v, 4));
            v = fmaxf(v, __shfl_xor_sync(0xffffffffu, v, 8));
            v = fmaxf(v, __shfl_xor_sync(0xffffffffu, v, 16));
            if (lane < 4) {
                int c = nb + sub * 8 + 2 * lane + j;
                g_xb[(size_t)bs * TOK + c] =
                    x[(size_t)bs * TOK + c] + fmaxf(v + g_c2[c], 0.f);
            }
        }
    }
}

// ---------------- qkv = xb @ w_qkv  [1024,256]x[256,768] --------------------
__global__ void qkv_kernel(const float* __restrict__ w_qkv) {
    __shared__ float As[16][65];   // +1 pad: kills 16-way store conflicts
    __shared__ float Bs[16][64];
    const int tid = threadIdx.x;
    const int tx = tid & 15, ty = tid >> 4;
    const int m0 = blockIdx.y * 64, n0 = blockIdx.x * 64;
    float acc[4][4] = {};
    float pa[4], pb[4];
#pragma unroll
    for (int i = 0; i < 4; i++) {
        int idx = tid + i * 256;
        pa[i] = g_xb[(size_t)(m0 + (idx >> 4)) * TOK + (idx & 15)];
        pb[i] = w_qkv[(size_t)(idx >> 6) * 768 + n0 + (idx & 63)];
    }
    for (int k0 = 0; k0 < TOK; k0 += 16) {
#pragma unroll
        for (int i = 0; i < 4; i++) {
            int idx = tid + i * 256;
            As[idx & 15][idx >> 4] = pa[i];
            Bs[idx >> 6][idx & 63] = pb[i];
        }
        __syncthreads();
        if (k0 + 16 < TOK) {
#pragma unroll
            for (int i = 0; i < 4; i++) {
                int idx = tid + i * 256;
                pa[i] = g_xb[(size_t)(m0 + (idx >> 4)) * TOK + k0 + 16 + (idx & 15)];
                pb[i] = w_qkv[(size_t)(k0 + 16 + (idx >> 6)) * 768 + n0 + (idx & 63)];
            }
        }
#pragma unroll
        for (int kk = 0; kk < 16; kk++) {
            float a[4], b[4];
#pragma unroll
            for (int i = 0; i < 4; i++) { a[i] = As[kk][ty * 4 + i]; b[i] = Bs[kk][tx * 4 + i]; }
#pragma unroll
            for (int i = 0; i < 4; i++)
#pragma unroll
                for (int j = 0; j < 4; j++) acc[i][j] = fmaf(a[i], b[j], acc[i][j]);
        }
        __syncthreads();
    }
#pragma unroll
    for (int i = 0; i < 4; i++)
#pragma unroll
        for (int j = 0; j < 4; j++)
            g_qkv[(size_t)(m0 + ty * 4 + i) * 768 + n0 + tx * 4 + j] = acc[i][j];
}

// ---------------- dots = q @ k^T * scale  (32x64 tiles, 128 thr) ------------
__global__ __launch_bounds__(128) void dots_kernel() {
    __shared__ float As[16][33];
    __shared__ float Bs[16][65];
    const int tid = threadIdx.x;
    const int tx = tid & 15, ty = tid >> 4;
    const int b = blockIdx.z;
    const int m0 = blockIdx.x * 32, n0 = blockIdx.y * 64;
    const float* q = g_qkv + (size_t)b * TT * 768;
    const float* k = g_qkv + (size_t)b * TT * 768 + INNER;
    float acc[4][4] = {};
    float pa[4], pb[8];
#pragma unroll
    for (int i = 0; i < 4; i++) {
        int idx = tid + i * 128;
        pa[i] = q[(size_t)(m0 + (idx >> 4)) * 768 + (idx & 15)];
    }
#pragma unroll
    for (int i = 0; i < 8; i++) {
        int idx = tid + i * 128;
        pb[i] = k[(size_t)(n0 + (idx >> 4)) * 768 + (idx & 15)];
    }
    for (int k0 = 0; k0 < INNER; k0 += 16) {
#pragma unroll
        for (int i = 0; i < 4; i++) { int idx = tid + i * 128; As[idx & 15][idx >> 4] = pa[i]; }
#pragma unroll
        for (int i = 0; i < 8; i++) { int idx = tid + i * 128; Bs[idx & 15][idx >> 4] = pb[i]; }
        __syncthreads();
        if (k0 + 16 < INNER) {
#pragma unroll
            for (int i = 0; i < 4; i++) {
                int idx = tid + i * 128;
                pa[i] = q[(size_t)(m0 + (idx >> 4)) * 768 + k0 + 16 + (idx & 15)];
            }
#pragma unroll
            for (int i = 0; i < 8; i++) {
                int idx = tid + i * 128;
                pb[i] = k[(size_t)(n0 + (idx >> 4)) * 768 + k0 + 16 + (idx & 15)];
            }
        }
#pragma unroll
        for (int kk = 0; kk < 16; kk++) {
            float a[4], bb[4];
#pragma unroll
            for (int i = 0; i < 4; i++) { a[i] = As[kk][ty * 4 + i]; bb[i] = Bs[kk][tx * 4 + i]; }
#pragma unroll
            for (int i = 0; i < 4; i++)
#pragma unroll
                for (int j = 0; j < 4; j++) acc[i][j] = fmaf(a[i], bb[j], acc[i][j]);
        }
        __syncthreads();
    }
    float* dst = g_dots + (size_t)b * TT * TT;
#pragma unroll
    for (int i = 0; i < 4; i++)
#pragma unroll
        for (int j = 0; j < 4; j++)
            dst[(size_t)(m0 + ty * 4 + i) * TT + n0 + tx * 4 + j] = acc[i][j] * ATT_SCALE;
}

// ---------------- row softmax over 512 --------------------------------------
__global__ void softmax_kernel() {
    const int row = blockIdx.x;
    float* p = g_dots + (size_t)row * TT;
    const int tid = threadIdx.x;
    const int w = tid >> 5, l = tid & 31;
    float v[4];
#pragma unroll
    for (int i = 0; i < 4; i++) v[i] = p[tid + i * 128];
    float m = fmaxf(fmaxf(v[0], v[1]), fmaxf(v[2], v[3]));
#pragma unroll
    for (int o = 16; o; o >>= 1) m = fmaxf(m, __shfl_xor_sync(0xffffffffu, m, o));
    __shared__ float red[4], red2[4];
    if (!l) red[w] = m;
    __syncthreads();
    m = fmaxf(fmaxf(red[0], red[1]), fmaxf(red[2], red[3]));
    float s = 0.f;
#pragma unroll
    for (int i = 0; i < 4; i++) { v[i] = __expf(v[i] - m); s += v[i]; }
#pragma unroll
    for (int o = 16; o; o >>= 1) s += __shfl_xor_sync(0xffffffffu, s, o);
    if (!l) red2[w] = s;
    __syncthreads();
    s = red2[0] + red2[1] + red2[2] + red2[3];
    float inv = 1.f / s;
#pragma unroll
    for (int i = 0; i < 4; i++) p[tid + i * 128] = v[i] * inv;
}

// ---------------- out = attn @ v  (32x64 tiles, 128 thr) --------------------
__global__ __launch_bounds__(128) void out_kernel(float* __restrict__ out) {
    __shared__ float As[16][33];
    __shared__ float Bs[16][65];
    const int tid = threadIdx.x;
    const int tx = tid & 15, ty = tid >> 4;
    const int b = blockIdx.z;
    const int m0 = blockIdx.y * 32, n0 = blockIdx.x * 64;
    const float* attn = g_dots + (size_t)b * TT * TT;
    const float* v = g_qkv + (size_t)b * TT * 768 + 2 * INNER;
    float acc[4][4] = {};
    float pa[4], pb[8];
#pragma unroll
    for (int i = 0; i < 4; i++) {
        int idx = tid + i * 128;
        pa[i] = attn[(size_t)(m0 + (idx >> 4)) * TT + (idx & 15)];
    }
#pragma unroll
    for (int i = 0; i < 8; i++) {
        int idx = tid + i * 128;
        pb[i] = v[(size_t)(idx >> 6) * 768 + n0 + (idx & 63)];
    }
    for (int k0 = 0; k0 < TT; k0 += 16) {
#pragma unroll
        for (int i = 0; i < 4; i++) { int idx = tid + i * 128; As[idx & 15][idx >> 4] = pa[i]; }
#pragma unroll
        for (int i = 0; i < 8; i++) { int idx = tid + i * 128; Bs[idx >> 6][idx & 63] = pb[i]; }
        __syncthreads();
        if (k0 + 16 < TT) {
#pragma unroll
            for (int i = 0; i < 4; i++) {
                int idx = tid + i * 128;
                pa[i] = attn[(size_t)(m0 + (idx >> 4)) * TT + k0 + 16 + (idx & 15)];
            }
#pragma unroll
            for (int i = 0; i < 8; i++) {
                int idx = tid + i * 128;
                pb[i] = v[(size_t)(k0 + 16 + (idx >> 6)) * 768 + n0 + (idx & 63)];
            }
        }
#pragma unroll
        for (int kk = 0; kk < 16; kk++) {
            float a[4], bb[4];
#pragma unroll
            for (int i = 0; i < 4; i++) { a[i] = As[kk][ty * 4 + i]; bb[i] = Bs[kk][tx * 4 + i]; }
#pragma unroll
            for (int i = 0; i < 4; i++)
#pragma unroll
                for (int j = 0; j < 4; j++) acc[i][j] = fmaf(a[i], bb[j], acc[i][j]);
        }
        __syncthreads();
    }
#pragma unroll
    for (int i = 0; i < 4; i++)
#pragma unroll
        for (int j = 0; j < 4; j++)
            out[(size_t)(b * TT + m0 + ty * 4 + i) * INNER + n0 + tx * 4 + j] = acc[i][j];
}

// ---------------- launch ------------------------------------------------------
extern "C" void kernel_launch(void* const* d_in, const int* in_sizes, int n_in,
                              void* d_out, int out_size) {
    const float* x     = (const float*)d_in[0];
    const float* r     = (const float*)d_in[1];
    const float* w1    = (const float*)d_in[2];
    const float* b1    = (const float*)d_in[3];
    const float* g1    = (const float*)d_in[4];
    const float* be1   = (const float*)d_in[5];
    const float* m1    = (const float*)d_in[6];
    const float* v1    = (const float*)d_in[7];
    const float* w2    = (const float*)d_in[8];
    const float* b2    = (const float*)d_in[9];
    const float* g2    = (const float*)d_in[10];
    const float* be2   = (const float*)d_in[11];
    const float* m2    = (const float*)d_in[12];
    const float* v2    = (const float*)d_in[13];
    const float* w_qkv = (const float*)d_in[14];
    float* out = (float*)d_out;

    setup_kernel<<<1, 256>>>(w1, b1, g1, be1, m1, v1, w2, b2, g2, be2, m2, v2);

    int smem_bytes = (TT * H1_STRIDE) * (int)sizeof(uint32_t); // 34816
    cudaFuncSetAttribute(fused_tpr_kernel, cudaFuncAttributeMaxDynamicSharedMemorySize, smem_bytes);
    fused_tpr_kernel<<<BD * TT, 256, smem_bytes>>>(r, x);

    qkv_kernel<<<dim3(768 / 64, 1024 / 64), 256>>>(w_qkv);
    dots_kernel<<<dim3(TT / 32, TT / 64, BD), 128>>>();
    softmax_kernel<<<BD * TT, 128>>>();
    out_kernel<<<dim3(INNER / 64, TT / 32, BD), 128>>>(out);
}